// round 11
// baseline (speedup 1.0000x reference)
#include <cuda_runtime.h>
#include <cuda_fp16.h>
#include <math.h>

#define B_  64
#define M_  16
#define A_  128
#define H_  128
#define P_  16
#define NATOM 100
#define NFP   2048
#define NTAB  (NATOM + NFP)     // 2148
#define RPB   17                // table rows per block in proj kernel

// Scratch (__device__ globals: allocation-free rule)
__device__ __half g_proj_h[NTAB * H_];    // projected tables, fp16 (0.55 MB, L2-resident)
__device__ float  g_mol[B_ * M_ * H_];    // per-molecule mean embeddings

// ---------------------------------------------------------------------------
// Kernel 1: projected tables -> g_proj_h (fp16).  (R9 version — best measured)
// Blocks 0..5: 100 atom rows (+b_in, W top half). Blocks 6..127: 2048 fp rows
// (W bottom half), 17 rows each. 1024 threads:
// h = tid&127 (out col), ks = (tid>>7)&3 (32 K-steps), rh = tid>>9 (row half).
// ---------------------------------------------------------------------------
__global__ __launch_bounds__(1024, 1)
void proj_kernel(const float* __restrict__ atom_emb,
                 const float* __restrict__ fp_emb,
                 const float* __restrict__ W_in,
                 const float* __restrict__ b_in) {
    __shared__ __align__(16) float s_eT[2560];            // [d][r] stride 20
    __shared__ __align__(16) float s_p[4 * RPB * H_];     // [ks][r][h]

    const int tid = threadIdx.x;
    const int blk = blockIdx.x;
    const int h  = tid & 127;
    const int ks = (tid >> 7) & 3;
    const int rh = tid >> 9;
    const int r0 = rh ? 8 : 0;
    const bool is_atom = (blk < 6);
    const int lrow0 = is_atom ? blk * RPB : (blk - 6) * RPB;
    const int nrows = is_atom ? NATOM : NFP;
    const int wbase = is_atom ? 0 : (H_ * H_);

    for (int i = tid; i < RPB * H_; i += 1024) {
        int r = i >> 7, d = i & 127;
        int t = lrow0 + r;
        float v = 0.0f;
        if (t < nrows) v = is_atom ? atom_emb[t * H_ + d] : fp_emb[t * H_ + d];
        s_eT[d * 20 + r] = v;
    }
    __syncthreads();

    const float* __restrict__ Wp = W_in + wbase + h;
    const int d0 = ks * 32;

    float acc[9];
    #pragma unroll
    for (int r = 0; r < 9; r++) acc[r] = 0.0f;

    #pragma unroll
    for (int chunk = 0; chunk < 4; chunk++) {
        float wreg[8];                                    // independent LDG batch
        #pragma unroll
        for (int i = 0; i < 8; i++) wreg[i] = Wp[(d0 + chunk * 8 + i) * H_];

        #pragma unroll
        for (int dd = 0; dd < 8; dd++) {
            const float w = wreg[dd];
            const float* e = s_eT + (d0 + chunk * 8 + dd) * 20 + r0;
            const float4 e0 = *(const float4*)(e);
            const float4 e1 = *(const float4*)(e + 4);
            acc[0] += e0.x * w; acc[1] += e0.y * w; acc[2] += e0.z * w; acc[3] += e0.w * w;
            acc[4] += e1.x * w; acc[5] += e1.y * w; acc[6] += e1.z * w; acc[7] += e1.w * w;
            if (rh) acc[8] += e[8] * w;                   // 17th row (upper half only)
        }
    }

    const int nr = rh ? 9 : 8;
    #pragma unroll
    for (int r = 0; r < 9; r++)
        if (r < nr) s_p[(ks * RPB + r0 + r) * H_ + h] = acc[r];
    __syncthreads();

    const int NP = RPB * H_;
    for (int i = tid; i < NP; i += 1024) {
        int r = i >> 7, hc = i & 127;
        int t = lrow0 + r;
        if (t < nrows) {
            float v = s_p[i] + s_p[NP + i] + s_p[2 * NP + i] + s_p[3 * NP + i];
            if (is_atom) g_proj_h[t * H_ + hc] = __float2half(v + b_in[hc]);
            else         g_proj_h[(NATOM + t) * H_ + hc] = __float2half(v);
        }
    }
}

// ---------------------------------------------------------------------------
// Kernel 2: per-molecule mean of relu(A_proj[af] + F_proj[fp]).
// Grid 512 x 256 threads: 2 molecules/block, 8 warps, 32 atoms/warp.
// NEW: the 100-row atom table (25.6 KB fp16) is copied to shared memory per
// block; atom gathers become LDS.64 with zero L2 traffic. fp gathers stay L2.
// ---------------------------------------------------------------------------
__global__ __launch_bounds__(256)
void mol_kernel(const int* __restrict__ atom_features,
                const int* __restrict__ fingerprints) {
    __shared__ __align__(16) __half s_atab[NATOM * H_];   // 25.6 KB
    __shared__ __align__(16) float  s_part[8 * H_];       // 4 KB

    const int tid  = threadIdx.x;
    const int w    = tid >> 5;                            // 0..7
    const int lane = tid & 31;
    const int ml   = w >> 2;                              // molecule-in-block 0..1
    const int q    = w & 3;                               // atom quarter
    const int bm   = blockIdx.x * 2 + ml;

    // Copy atom table into smem: 1600 uint4 (16B) chunks, coalesced stream.
    {
        const uint4* src = (const uint4*)g_proj_h;
        uint4* dst = (uint4*)s_atab;
        #pragma unroll
        for (int i = tid; i < (NATOM * H_ * 2) / 16; i += 256) dst[i] = src[i];
    }

    // Lane i holds atom (q*32+i)'s row bases (uint2 units).
    const int abase = bm * A_ + q * 32 + lane;
    const int ra = atom_features[abase] * (H_ / 4);                // smem uint2 idx
    const int rf = (NATOM + fingerprints[abase]) * (H_ / 4);       // global uint2 idx
    __syncthreads();

    const uint2* __restrict__ gp = (const uint2*)g_proj_h;
    const uint2* at = (const uint2*)s_atab;
    const __half2 zero2 = __float2half2_rn(0.0f);

    float4 acc = make_float4(0.0f, 0.0f, 0.0f, 0.0f);
    #pragma unroll 8
    for (int a = 0; a < 32; a++) {
        int ia = __shfl_sync(0xFFFFFFFFu, ra, a);
        int If = __shfl_sync(0xFFFFFFFFu, rf, a);
        uint2 ua = at[ia + lane];                 // LDS.64, conflict-free (256B row)
        uint2 uf = gp[If + lane];                 // LDG.64 from L2
        __half2 va0 = *(__half2*)&ua.x, va1 = *(__half2*)&ua.y;
        __half2 vf0 = *(__half2*)&uf.x, vf1 = *(__half2*)&uf.y;
        __half2 s0 = __hmax2(__hadd2(va0, vf0), zero2);
        __half2 s1 = __hmax2(__hadd2(va1, vf1), zero2);
        float2 p0 = __half22float2(s0);
        float2 p1 = __half22float2(s1);
        acc.x += p0.x; acc.y += p0.y; acc.z += p1.x; acc.w += p1.y;
    }
    ((float4*)s_part)[w * 32 + lane] = acc;       // one STS.128, conflict-free
    __syncthreads();

    {
        int m = tid >> 7, d = tid & 127;
        float v = (s_part[(4 * m + 0) * H_ + d] + s_part[(4 * m + 1) * H_ + d] +
                   s_part[(4 * m + 2) * H_ + d] + s_part[(4 * m + 3) * H_ + d])
                  * (1.0f / (float)A_);
        g_mol[(blockIdx.x * 2 + m) * H_ + d] = v;
    }
}

// ---------------------------------------------------------------------------
// Kernel 3: mixing weights + phys mix + LayerNorm + 2-layer MLP head.
// One block per batch item; 256 threads (W1 GEMV 2-way K-split).
// ---------------------------------------------------------------------------
__global__ __launch_bounds__(256)
void head_kernel(const float* __restrict__ phys,
                 const float* __restrict__ ratios,
                 const float* __restrict__ ln_g,
                 const float* __restrict__ ln_b,
                 const float* __restrict__ W1,
                 const float* __restrict__ b1,
                 const float* __restrict__ W2,
                 const float* __restrict__ b2,
                 float* __restrict__ out) {
    const int b   = blockIdx.x;
    const int tid = threadIdx.x;
    const int h   = tid & 127;
    const int ks  = tid >> 7;          // 0,1: K-split of the W1 GEMV

    __shared__ float s_w[M_];
    __shared__ float s_z[H_ + P_];
    __shared__ float s_zn[H_ + P_];
    __shared__ float s_red[8];
    __shared__ float s_t[2][H_];

    if (tid < M_) s_w[tid] = ratios[b * M_ + tid];
    __syncthreads();
    if (tid == 0) {
        float s = 0.0f;
        #pragma unroll
        for (int m = 0; m < M_; m++) s += s_w[m];
        float inv = 1.0f / (s + 1e-8f);
        #pragma unroll
        for (int m = 0; m < M_; m++) s_w[m] *= inv;
    }
    __syncthreads();

    if (tid < H_) {
        float acc = 0.0f;
        #pragma unroll
        for (int m = 0; m < M_; m++) acc += s_w[m] * g_mol[(b * M_ + m) * H_ + tid];
        s_z[tid] = acc;
        if (tid < P_) {
            float accp = 0.0f;
            #pragma unroll
            for (int m = 0; m < M_; m++) {
                float v = phys[(b * M_ + m) * P_ + tid];
                if (v != v) v = 0.0f;
                else if (isinf(v)) v = (v > 0.0f) ? 1000.0f : -1000.0f;
                accp += s_w[m] * v;
            }
            s_z[H_ + tid] = accp;
        }
    }
    __syncthreads();

    if (tid < H_) {
        float x  = s_z[tid];
        float x2 = x * x;
        if (tid < P_) { float e = s_z[H_ + tid]; x += e; x2 += e * e; }
        #pragma unroll
        for (int o = 16; o > 0; o >>= 1) {
            x  += __shfl_xor_sync(0xFFFFFFFFu, x,  o);
            x2 += __shfl_xor_sync(0xFFFFFFFFu, x2, o);
        }
        int warp = tid >> 5;
        if ((tid & 31) == 0) { s_red[warp] = x; s_red[4 + warp] = x2; }
    }
    __syncthreads();

    if (tid < H_) {
        float sum  = s_red[0] + s_red[1] + s_red[2] + s_red[3];
        float sum2 = s_red[4] + s_red[5] + s_red[6] + s_red[7];
        const float N = (float)(H_ + P_);
        float mu  = sum / N;
        float var = sum2 / N - mu * mu;
        float rstd = rsqrtf(var + 1e-5f);
        s_zn[tid] = (s_z[tid] - mu) * rstd * ln_g[tid] + ln_b[tid];
        if (tid < P_) s_zn[H_ + tid] = (s_z[H_ + tid] - mu) * rstd * ln_g[H_ + tid] + ln_b[H_ + tid];
    }
    __syncthreads();

    // W1 GEMV, 2-way K-split: ks=0 -> d in [0,72), ks=1 -> d in [72,144)
    {
        float t = (ks == 0) ? b1[h] : 0.0f;
        const int dlo = ks * 72;
        #pragma unroll 8
        for (int d = 0; d < 72; d++) t += s_zn[dlo + d] * W1[(dlo + d) * H_ + h];
        s_t[ks][h] = t;
    }
    __syncthreads();

    if (tid < H_) {
        float r = fmaxf(s_t[0][tid] + s_t[1][tid], 0.0f) * W2[tid];
        #pragma unroll
        for (int o = 16; o > 0; o >>= 1) r += __shfl_xor_sync(0xFFFFFFFFu, r, o);
        int warp = tid >> 5;
        if ((tid & 31) == 0) s_red[warp] = r;
    }
    __syncthreads();
    if (tid == 0) {
        float y = s_red[0] + s_red[1] + s_red[2] + s_red[3] + b2[0];
        if (y != y) y = 0.0f;
        else if (isinf(y)) y = (y > 0.0f) ? 3.4028234663852886e38f : -3.4028234663852886e38f;
        out[b] = y;
    }
}

extern "C" void kernel_launch(void* const* d_in, const int* in_sizes, int n_in,
                              void* d_out, int out_size) {
    const int*   atom_features = (const int*)  d_in[0];
    const int*   fingerprints  = (const int*)  d_in[1];
    const float* phys          = (const float*)d_in[2];
    const float* ratios        = (const float*)d_in[3];
    const float* atom_emb      = (const float*)d_in[4];
    const float* fp_emb        = (const float*)d_in[5];
    const float* W_in          = (const float*)d_in[6];
    const float* b_in          = (const float*)d_in[7];
    const float* ln_g          = (const float*)d_in[8];
    const float* ln_b          = (const float*)d_in[9];
    const float* W1            = (const float*)d_in[10];
    const float* b1            = (const float*)d_in[11];
    const float* W2            = (const float*)d_in[12];
    const float* b2            = (const float*)d_in[13];
    float* out = (float*)d_out;

    proj_kernel<<<128, 1024>>>(atom_emb, fp_emb, W_in, b_in);
    mol_kernel<<<512, 256>>>(atom_features, fingerprints);
    head_kernel<<<B_, 256>>>(phys, ratios, ln_g, ln_b, W1, b1, W2, b2, out);
}

// round 12
// speedup vs baseline: 1.0182x; 1.0182x over previous
#include <cuda_runtime.h>
#include <cuda_fp16.h>
#include <math.h>

#define B_  64
#define M_  16
#define A_  128
#define H_  128
#define P_  16
#define NATOM 100
#define NFP   2048
#define NTAB  (NATOM + NFP)     // 2148
#define RPB   16                // table rows per block in proj kernel
#define PROJ_GRID 135           // 7 atom blocks + 128 fp blocks (one wave)

// Dynamic smem layout for proj (floats):
//   s_W  [0, 16384)          64 KB  W-half, staged coalesced
//   s_eT [16384, 18432)       8 KB  E tile transposed [d][r], stride 16
//   s_p  [18432, 26624)      32 KB  K-slice partials [ks][r][h]
#define PROJ_SMEM_BYTES (26624 * 4)

// Scratch (__device__ globals: allocation-free rule)
__device__ __half g_proj_h[NTAB * H_];    // projected tables, fp16 (0.55 MB, L2-resident)
__device__ float  g_mol[B_ * M_ * H_];    // per-molecule mean embeddings

// ---------------------------------------------------------------------------
// Kernel 1: projected tables -> g_proj_h (fp16).
// Blocks 0..6: 100 atom rows (+b_in, W top half). Blocks 7..134: 2048 fp rows
// (W bottom half), 16 rows each. 1024 threads:
// h = tid&127 (out col), ks = (tid>>7)&3 (32 K-steps), rh = tid>>9 (row half).
// W-half staged in smem (4 coalesced LDG.128/thread); mainloop is pure LDS+FMA.
// ---------------------------------------------------------------------------
__global__ __launch_bounds__(1024, 1)
void proj_kernel(const float* __restrict__ atom_emb,
                 const float* __restrict__ fp_emb,
                 const float* __restrict__ W_in,
                 const float* __restrict__ b_in) {
    extern __shared__ __align__(16) float smem[];
    float* s_W  = smem;              // [d][h] 128x128
    float* s_eT = smem + 16384;      // [d][r] stride 16
    float* s_p  = smem + 18432;      // [ks][r][h]

    const int tid = threadIdx.x;
    const int blk = blockIdx.x;
    const int h  = tid & 127;
    const int ks = (tid >> 7) & 3;
    const int rh = tid >> 9;
    const int r0 = rh * 8;
    const bool is_atom = (blk < 7);
    const int lrow0 = is_atom ? blk * RPB : (blk - 7) * RPB;
    const int nrows = is_atom ? NATOM : NFP;
    const float* __restrict__ Whalf = W_in + (is_atom ? 0 : H_ * H_);

    // Stage W-half: 16384 floats = 4096 float4, coalesced.
    #pragma unroll
    for (int i = tid; i < 4096; i += 1024)
        ((float4*)s_W)[i] = ((const float4*)Whalf)[i];

    // Load E tile transposed (zero-fill out-of-range atom rows).
    #pragma unroll
    for (int i = tid; i < RPB * H_; i += 1024) {
        int r = i >> 7, d = i & 127;
        int t = lrow0 + r;
        float v = 0.0f;
        if (t < nrows) v = is_atom ? atom_emb[t * H_ + d] : fp_emb[t * H_ + d];
        s_eT[d * 16 + r] = v;
    }
    __syncthreads();

    const int d0 = ks * 32;
    float acc[8];
    #pragma unroll
    for (int r = 0; r < 8; r++) acc[r] = 0.0f;

    #pragma unroll 8
    for (int dd = 0; dd < 32; dd++) {
        const int d = d0 + dd;
        const float w = s_W[d * H_ + h];                  // LDS.32, conflict-free
        const float* e = s_eT + d * 16 + r0;              // broadcast
        const float4 e0 = *(const float4*)(e);
        const float4 e1 = *(const float4*)(e + 4);
        acc[0] += e0.x * w; acc[1] += e0.y * w; acc[2] += e0.z * w; acc[3] += e0.w * w;
        acc[4] += e1.x * w; acc[5] += e1.y * w; acc[6] += e1.z * w; acc[7] += e1.w * w;
    }

    #pragma unroll
    for (int r = 0; r < 8; r++) s_p[(ks * RPB + r0 + r) * H_ + h] = acc[r];
    __syncthreads();

    // Reduce 4 K-slices, store fp16: 2048 outputs / 1024 threads = 2 each.
    const int NP = RPB * H_;
    #pragma unroll
    for (int i = tid; i < NP; i += 1024) {
        int r = i >> 7, hc = i & 127;
        int t = lrow0 + r;
        if (t < nrows) {
            float v = s_p[i] + s_p[NP + i] + s_p[2 * NP + i] + s_p[3 * NP + i];
            if (is_atom) g_proj_h[t * H_ + hc] = __float2half(v + b_in[hc]);
            else         g_proj_h[(NATOM + t) * H_ + hc] = __float2half(v);
        }
    }
}

// ---------------------------------------------------------------------------
// Kernel 2: per-molecule mean of relu(A_proj[af] + F_proj[fp]).  (R9 form)
// Grid 512 x 256 threads: 2 molecules/block, 8 warps, 32 atoms/warp.
// Lane i holds atom i's row bases; __shfl broadcasts per iteration. One warp
// reads a 256B fp16 row per LDG.64. Partials stored via STS.128.
// ---------------------------------------------------------------------------
__global__ __launch_bounds__(256, 8)
void mol_kernel(const int* __restrict__ atom_features,
                const int* __restrict__ fingerprints) {
    __shared__ __align__(16) float s_part[8 * H_];

    const int tid  = threadIdx.x;
    const int w    = tid >> 5;                            // 0..7
    const int lane = tid & 31;
    const int ml   = w >> 2;                              // molecule-in-block 0..1
    const int q    = w & 3;                               // atom quarter
    const int bm   = blockIdx.x * 2 + ml;

    const int abase = bm * A_ + q * 32 + lane;
    const int ra = atom_features[abase] * (H_ / 4);       // uint2-row base
    const int rf = (NATOM + fingerprints[abase]) * (H_ / 4);

    const uint2* __restrict__ gp = (const uint2*)g_proj_h;
    const __half2 zero2 = __float2half2_rn(0.0f);

    float4 acc = make_float4(0.0f, 0.0f, 0.0f, 0.0f);
    #pragma unroll 8
    for (int a = 0; a < 32; a++) {
        int ia = __shfl_sync(0xFFFFFFFFu, ra, a);
        int If = __shfl_sync(0xFFFFFFFFu, rf, a);
        uint2 ua = gp[ia + lane];
        uint2 uf = gp[If + lane];
        __half2 va0 = *(__half2*)&ua.x, va1 = *(__half2*)&ua.y;
        __half2 vf0 = *(__half2*)&uf.x, vf1 = *(__half2*)&uf.y;
        __half2 s0 = __hmax2(__hadd2(va0, vf0), zero2);
        __half2 s1 = __hmax2(__hadd2(va1, vf1), zero2);
        float2 p0 = __half22float2(s0);
        float2 p1 = __half22float2(s1);
        acc.x += p0.x; acc.y += p0.y; acc.z += p1.x; acc.w += p1.y;
    }
    ((float4*)s_part)[w * 32 + lane] = acc;               // STS.128, conflict-free
    __syncthreads();

    {
        int m = tid >> 7, d = tid & 127;
        float v = (s_part[(4 * m + 0) * H_ + d] + s_part[(4 * m + 1) * H_ + d] +
                   s_part[(4 * m + 2) * H_ + d] + s_part[(4 * m + 3) * H_ + d])
                  * (1.0f / (float)A_);
        g_mol[(blockIdx.x * 2 + m) * H_ + d] = v;
    }
}

// ---------------------------------------------------------------------------
// Kernel 3: mixing weights + phys mix + LayerNorm + 2-layer MLP head.
// One block per batch item; 256 threads (W1 GEMV 2-way K-split).
// ---------------------------------------------------------------------------
__global__ __launch_bounds__(256)
void head_kernel(const float* __restrict__ phys,
                 const float* __restrict__ ratios,
                 const float* __restrict__ ln_g,
                 const float* __restrict__ ln_b,
                 const float* __restrict__ W1,
                 const float* __restrict__ b1,
                 const float* __restrict__ W2,
                 const float* __restrict__ b2,
                 float* __restrict__ out) {
    const int b   = blockIdx.x;
    const int tid = threadIdx.x;
    const int h   = tid & 127;
    const int ks  = tid >> 7;          // 0,1: K-split of the W1 GEMV

    __shared__ float s_w[M_];
    __shared__ float s_z[H_ + P_];
    __shared__ float s_zn[H_ + P_];
    __shared__ float s_red[8];
    __shared__ float s_t[2][H_];

    if (tid < M_) s_w[tid] = ratios[b * M_ + tid];
    __syncthreads();
    if (tid == 0) {
        float s = 0.0f;
        #pragma unroll
        for (int m = 0; m < M_; m++) s += s_w[m];
        float inv = 1.0f / (s + 1e-8f);
        #pragma unroll
        for (int m = 0; m < M_; m++) s_w[m] *= inv;
    }
    __syncthreads();

    if (tid < H_) {
        float acc = 0.0f;
        #pragma unroll
        for (int m = 0; m < M_; m++) acc += s_w[m] * g_mol[(b * M_ + m) * H_ + tid];
        s_z[tid] = acc;
        if (tid < P_) {
            float accp = 0.0f;
            #pragma unroll
            for (int m = 0; m < M_; m++) {
                float v = phys[(b * M_ + m) * P_ + tid];
                if (v != v) v = 0.0f;
                else if (isinf(v)) v = (v > 0.0f) ? 1000.0f : -1000.0f;
                accp += s_w[m] * v;
            }
            s_z[H_ + tid] = accp;
        }
    }
    __syncthreads();

    if (tid < H_) {
        float x  = s_z[tid];
        float x2 = x * x;
        if (tid < P_) { float e = s_z[H_ + tid]; x += e; x2 += e * e; }
        #pragma unroll
        for (int o = 16; o > 0; o >>= 1) {
            x  += __shfl_xor_sync(0xFFFFFFFFu, x,  o);
            x2 += __shfl_xor_sync(0xFFFFFFFFu, x2, o);
        }
        int warp = tid >> 5;
        if ((tid & 31) == 0) { s_red[warp] = x; s_red[4 + warp] = x2; }
    }
    __syncthreads();

    if (tid < H_) {
        float sum  = s_red[0] + s_red[1] + s_red[2] + s_red[3];
        float sum2 = s_red[4] + s_red[5] + s_red[6] + s_red[7];
        const float N = (float)(H_ + P_);
        float mu  = sum / N;
        float var = sum2 / N - mu * mu;
        float rstd = rsqrtf(var + 1e-5f);
        s_zn[tid] = (s_z[tid] - mu) * rstd * ln_g[tid] + ln_b[tid];
        if (tid < P_) s_zn[H_ + tid] = (s_z[H_ + tid] - mu) * rstd * ln_g[H_ + tid] + ln_b[H_ + tid];
    }
    __syncthreads();

    // W1 GEMV, 2-way K-split: ks=0 -> d in [0,72), ks=1 -> d in [72,144)
    {
        float t = (ks == 0) ? b1[h] : 0.0f;
        const int dlo = ks * 72;
        #pragma unroll 8
        for (int d = 0; d < 72; d++) t += s_zn[dlo + d] * W1[(dlo + d) * H_ + h];
        s_t[ks][h] = t;
    }
    __syncthreads();

    if (tid < H_) {
        float r = fmaxf(s_t[0][tid] + s_t[1][tid], 0.0f) * W2[tid];
        #pragma unroll
        for (int o = 16; o > 0; o >>= 1) r += __shfl_xor_sync(0xFFFFFFFFu, r, o);
        int warp = tid >> 5;
        if ((tid & 31) == 0) s_red[warp] = r;
    }
    __syncthreads();
    if (tid == 0) {
        float y = s_red[0] + s_red[1] + s_red[2] + s_red[3] + b2[0];
        if (y != y) y = 0.0f;
        else if (isinf(y)) y = (y > 0.0f) ? 3.4028234663852886e38f : -3.4028234663852886e38f;
        out[b] = y;
    }
}

extern "C" void kernel_launch(void* const* d_in, const int* in_sizes, int n_in,
                              void* d_out, int out_size) {
    const int*   atom_features = (const int*)  d_in[0];
    const int*   fingerprints  = (const int*)  d_in[1];
    const float* phys          = (const float*)d_in[2];
    const float* ratios        = (const float*)d_in[3];
    const float* atom_emb      = (const float*)d_in[4];
    const float* fp_emb        = (const float*)d_in[5];
    const float* W_in          = (const float*)d_in[6];
    const float* b_in          = (const float*)d_in[7];
    const float* ln_g          = (const float*)d_in[8];
    const float* ln_b          = (const float*)d_in[9];
    const float* W1            = (const float*)d_in[10];
    const float* b1            = (const float*)d_in[11];
    const float* W2            = (const float*)d_in[12];
    const float* b2            = (const float*)d_in[13];
    float* out = (float*)d_out;

    static int smem_configured = 0;
    if (!smem_configured) {
        cudaFuncSetAttribute(proj_kernel,
                             cudaFuncAttributeMaxDynamicSharedMemorySize,
                             PROJ_SMEM_BYTES);
        smem_configured = 1;
    }

    proj_kernel<<<PROJ_GRID, 1024, PROJ_SMEM_BYTES>>>(atom_emb, fp_emb, W_in, b_in);
    mol_kernel<<<512, 256>>>(atom_features, fingerprints);
    head_kernel<<<B_, 256>>>(phys, ratios, ln_g, ln_b, W1, b1, W2, b2, out);
}